// round 14
// baseline (speedup 1.0000x reference)
#include <cuda_runtime.h>
#include <cstdint>

#define BT_TOT 192
#define NN 64
#define DM 128
#define TT 96
#define SCOLS 320   // 0-127: G=Z@(Wq Wk^T), 128-255: Vt=Z@(Wv Wth), 256-287: qh, 288-319: kh

__device__ float g_Wpart[4][128 * SCOLS];   // K-split partial products of Wcat
__device__ float g_S1[12288 * SCOLS];
__device__ float g_C[192 * 64 * 64];        // content logits (pre-scaled)

typedef unsigned long long u64;
__device__ __forceinline__ u64 pk2(float lo, float hi) {
    u64 r; asm("mov.b64 %0,{%1,%2};" : "=l"(r) : "f"(lo), "f"(hi)); return r;
}
__device__ __forceinline__ float2 up2(u64 v) {
    float2 f; asm("mov.b64 {%0,%1},%2;" : "=f"(f.x), "=f"(f.y) : "l"(v)); return f;
}
__device__ __forceinline__ u64 fma2_(u64 a, u64 b, u64 c) {
    u64 d; asm("fma.rn.f32x2 %0,%1,%2,%3;" : "=l"(d) : "l"(a), "l"(b), "l"(c)); return d;
}
__device__ __forceinline__ u64 add2_(u64 a, u64 b) {
    u64 d; asm("add.rn.f32x2 %0,%1,%2;" : "=l"(d) : "l"(a), "l"(b)); return d;
}

// ---------------- K0: partial Wcat products, 4-way K-split, 160 blocks ----------------
__global__ void __launch_bounds__(256) k0_fuse(
    const float* __restrict__ Wq, const float* __restrict__ Wk,
    const float* __restrict__ Wv, const float* __restrict__ W1,
    const float* __restrict__ Wth) {
    __shared__ float As[32 * 36];   // [row][m']
    __shared__ float Bs[32 * 36];   // [col][m']
    int ct = blockIdx.x;   // 0..9
    int rt = blockIdx.y;   // 0..3
    int kh = blockIdx.z;   // 0..3  (K chunk)
    int r0 = rt * 32, mo = kh * 32;
    int tid = threadIdx.x;

    const float* Asrc = (ct < 4) ? Wq : (ct < 8) ? Wv : (ct == 8) ? Wq : Wk;
    {
        int i = tid >> 3, c4 = (tid & 7) * 4;
        *(float4*)(As + i * 36 + c4) = *(const float4*)(Asrc + (r0 + i) * 128 + mo + c4);
    }
    if (ct < 4) {
        int c = tid >> 3, m4 = (tid & 7) * 4;
        *(float4*)(Bs + c * 36 + m4) = *(const float4*)(Wk + (ct * 32 + c) * 128 + mo + m4);
    } else if (ct < 8) {
        int m = tid >> 3, c4 = (tid & 7) * 4;
        float4 v = *(const float4*)(Wth + (mo + m) * 128 + (ct - 4) * 32 + c4);
        Bs[(c4 + 0) * 36 + m] = v.x;
        Bs[(c4 + 1) * 36 + m] = v.y;
        Bs[(c4 + 2) * 36 + m] = v.z;
        Bs[(c4 + 3) * 36 + m] = v.w;
    } else {
        int off = (ct == 9) ? 128 : 0;
        int m = tid >> 3, c4 = (tid & 7) * 4;
        float4 v = *(const float4*)(W1 + (off + mo + m) * 32 + c4);
        Bs[(c4 + 0) * 36 + m] = v.x;
        Bs[(c4 + 1) * 36 + m] = v.y;
        Bs[(c4 + 2) * 36 + m] = v.z;
        Bs[(c4 + 3) * 36 + m] = v.w;
    }
    __syncthreads();

    int tx = tid & 15, ty = tid >> 4;
    u64 a00 = 0, a01 = 0, a10 = 0, a11 = 0;
    #pragma unroll
    for (int m = 0; m < 32; m += 4) {
        float4 x0 = *(float4*)(As + (ty * 2 + 0) * 36 + m);
        float4 x1 = *(float4*)(As + (ty * 2 + 1) * 36 + m);
        float4 y0 = *(float4*)(Bs + (tx * 2 + 0) * 36 + m);
        float4 y1 = *(float4*)(Bs + (tx * 2 + 1) * 36 + m);
        u64 x0a = pk2(x0.x, x0.y), x0b = pk2(x0.z, x0.w);
        u64 x1a = pk2(x1.x, x1.y), x1b = pk2(x1.z, x1.w);
        u64 y0a = pk2(y0.x, y0.y), y0b = pk2(y0.z, y0.w);
        u64 y1a = pk2(y1.x, y1.y), y1b = pk2(y1.z, y1.w);
        a00 = fma2_(x0a, y0a, a00); a00 = fma2_(x0b, y0b, a00);
        a01 = fma2_(x0a, y1a, a01); a01 = fma2_(x0b, y1b, a01);
        a10 = fma2_(x1a, y0a, a10); a10 = fma2_(x1b, y0b, a10);
        a11 = fma2_(x1a, y1a, a11); a11 = fma2_(x1b, y1b, a11);
    }
    float2 f;
    int orow = r0 + ty * 2, ocol = ct * 32 + tx * 2;
    float* wp = g_Wpart[kh];
    f = up2(a00); wp[(orow + 0) * SCOLS + ocol + 0] = f.x + f.y;
    f = up2(a01); wp[(orow + 0) * SCOLS + ocol + 1] = f.x + f.y;
    f = up2(a10); wp[(orow + 1) * SCOLS + ocol + 0] = f.x + f.y;
    f = up2(a11); wp[(orow + 1) * SCOLS + ocol + 1] = f.x + f.y;
}

// ---------------- TF32 helpers ----------------
__device__ __forceinline__ uint32_t f2tf(float f) {
    uint32_t u; asm("cvt.rna.tf32.f32 %0, %1;" : "=r"(u) : "f"(f)); return u;
}
__device__ __forceinline__ void mma_tf32(float* c, const uint32_t* a, const uint32_t* b) {
    asm volatile("mma.sync.aligned.m16n8k8.row.col.f32.tf32.tf32.f32 "
        "{%0,%1,%2,%3}, {%4,%5,%6,%7}, {%8,%9}, {%0,%1,%2,%3};"
        : "+f"(c[0]), "+f"(c[1]), "+f"(c[2]), "+f"(c[3])
        : "r"(a[0]), "r"(a[1]), "r"(a[2]), "r"(a[3]), "r"(b[0]), "r"(b[1]));
}

// ---------------- K1: S1 = Z @ Wcat via 3xTF32 tensor cores ----------------
#define K1_SMEM ((128*36*2 + 32*136*2) * 4)

__global__ void __launch_bounds__(256) k1_gemm(const float* __restrict__ x) {
    extern __shared__ uint32_t smk1[];
    uint32_t* Ah = smk1;                 // 128 x 36
    uint32_t* Al = Ah + 128 * 36;
    uint32_t* Bh = Al + 128 * 36;        // 32 x 136
    uint32_t* Bl = Bh + 32 * 136;

    int m0 = blockIdx.x * 128;
    int n0 = blockIdx.y * 128;
    int tid = threadIdx.x;
    int lane = tid & 31, warp = tid >> 5;
    int g = lane >> 2, t4 = lane & 3;
    int wm = warp >> 2, wn = warp & 3;
    int mb = wm * 64, nb = wn * 32;

    float c[4][4][4];
    #pragma unroll
    for (int im = 0; im < 4; im++)
        #pragma unroll
        for (int in_ = 0; in_ < 4; in_++)
            #pragma unroll
            for (int q = 0; q < 4; q++) c[im][in_][q] = 0.f;

    for (int kk = 0; kk < 128; kk += 32) {
        #pragma unroll
        for (int it = 0; it < 4; it++) {
            int idx = tid + it * 256;
            int i = idx >> 3, c4 = (idx & 7) * 4;
            int r = m0 + i;
            int bt = r >> 6, n = r & 63;
            int b = bt / 96, t = bt - b * 96;
            float4 v = *(const float4*)(x + (size_t)(((b * 64 + n) * 96 + t)) * 128 + kk + c4);
            float vv[4] = {v.x, v.y, v.z, v.w};
            #pragma unroll
            for (int q = 0; q < 4; q++) {
                uint32_t hi = f2tf(vv[q]);
                float lof = vv[q] - __uint_as_float(hi);
                Ah[i * 36 + c4 + q] = hi;
                Al[i * 36 + c4 + q] = f2tf(lof);
            }
        }
        #pragma unroll
        for (int it = 0; it < 4; it++) {
            int idx = tid + it * 256;
            int kr = idx >> 5, c4 = (idx & 31) * 4;
            int col = n0 + c4;
            float4 v = make_float4(0.f, 0.f, 0.f, 0.f);
            if (col < SCOLS) {
                size_t off = (size_t)(kk + kr) * SCOLS + col;
                float4 v0 = *(const float4*)(g_Wpart[0] + off);
                float4 v1 = *(const float4*)(g_Wpart[1] + off);
                float4 v2 = *(const float4*)(g_Wpart[2] + off);
                float4 v3 = *(const float4*)(g_Wpart[3] + off);
                v.x = (v0.x + v1.x) + (v2.x + v3.x);
                v.y = (v0.y + v1.y) + (v2.y + v3.y);
                v.z = (v0.z + v1.z) + (v2.z + v3.z);
                v.w = (v0.w + v1.w) + (v2.w + v3.w);
            }
            float vv[4] = {v.x, v.y, v.z, v.w};
            #pragma unroll
            for (int q = 0; q < 4; q++) {
                uint32_t hi = f2tf(vv[q]);
                float lof = vv[q] - __uint_as_float(hi);
                Bh[kr * 136 + c4 + q] = hi;
                Bl[kr * 136 + c4 + q] = f2tf(lof);
            }
        }
        __syncthreads();

        #pragma unroll
        for (int ks = 0; ks < 4; ks++) {
            int k0 = ks * 8;
            uint32_t ahi[4][4], alo[4][4], bhi[4][2], blo[4][2];
            #pragma unroll
            for (int im = 0; im < 4; im++) {
                int rA = (mb + im * 16 + g) * 36 + k0 + t4;
                int rA8 = rA + 8 * 36;
                ahi[im][0] = Ah[rA];      ahi[im][1] = Ah[rA8];
                ahi[im][2] = Ah[rA + 4];  ahi[im][3] = Ah[rA8 + 4];
                alo[im][0] = Al[rA];      alo[im][1] = Al[rA8];
                alo[im][2] = Al[rA + 4];  alo[im][3] = Al[rA8 + 4];
            }
            #pragma unroll
            for (int in_ = 0; in_ < 4; in_++) {
                int colB = nb + in_ * 8 + g;
                bhi[in_][0] = Bh[(k0 + t4) * 136 + colB];
                bhi[in_][1] = Bh[(k0 + t4 + 4) * 136 + colB];
                blo[in_][0] = Bl[(k0 + t4) * 136 + colB];
                blo[in_][1] = Bl[(k0 + t4 + 4) * 136 + colB];
            }
            #pragma unroll
            for (int im = 0; im < 4; im++)
                #pragma unroll
                for (int in_ = 0; in_ < 4; in_++) {
                    mma_tf32(c[im][in_], ahi[im], bhi[in_]);
                    mma_tf32(c[im][in_], alo[im], bhi[in_]);
                    mma_tf32(c[im][in_], ahi[im], blo[in_]);
                }
        }
        __syncthreads();
    }

    #pragma unroll
    for (int im = 0; im < 4; im++)
        #pragma unroll
        for (int in_ = 0; in_ < 4; in_++) {
            int row = m0 + mb + im * 16 + g;
            int col = n0 + nb + in_ * 8 + t4 * 2;
            if (col < SCOLS) {
                *(float2*)(g_S1 + (size_t)row * SCOLS + col) = make_float2(c[im][in_][0], c[im][in_][1]);
                *(float2*)(g_S1 + (size_t)(row + 8) * SCOLS + col) = make_float2(c[im][in_][2], c[im][in_][3]);
            }
        }
}

// ---------------- K1B: content[bt] = G @ Z^T (scaled), 3xTF32 ----------------
#define K1B_SMEM ((64*136*2 + 32*136*2) * 4)

__global__ void __launch_bounds__(256) k1b_content(const float* __restrict__ x) {
    extern __shared__ uint32_t smc[];
    uint32_t* Gh = smc;                  // 64 x 136
    uint32_t* Gl = Gh + 64 * 136;
    uint32_t* Zh = Gl + 64 * 136;        // 32 x 136
    uint32_t* Zl = Zh + 32 * 136;

    int bt = blockIdx.x;
    int b = bt / 96, t = bt - b * 96;
    int tid = threadIdx.x;
    int lane = tid & 31, warp = tid >> 5;
    int g = lane >> 2, t4 = lane & 3;
    int wi = warp >> 1, wj = warp & 1;

    const float* s1 = g_S1 + (size_t)(bt * 64) * SCOLS;
    #pragma unroll
    for (int it = 0; it < 8; it++) {
        int idx = tid + it * 256;
        int i = idx >> 5, c4 = (idx & 31) * 4;
        float4 v = *(const float4*)(s1 + (size_t)i * SCOLS + c4);
        float vv[4] = {v.x, v.y, v.z, v.w};
        #pragma unroll
        for (int q = 0; q < 4; q++) {
            uint32_t hi = f2tf(vv[q]);
            float lof = vv[q] - __uint_as_float(hi);
            Gh[i * 136 + c4 + q] = hi;
            Gl[i * 136 + c4 + q] = f2tf(lof);
        }
    }

    const float scale = 0.08838834764831845f;
    float* cbase = g_C + (size_t)bt * 4096;

    for (int jh = 0; jh < 2; jh++) {
        __syncthreads();
        #pragma unroll
        for (int it = 0; it < 4; it++) {
            int idx = tid + it * 256;
            int j = idx >> 5, c4 = (idx & 31) * 4;
            float4 v = *(const float4*)(x + (size_t)(((b * 64 + jh * 32 + j) * 96 + t)) * 128 + c4);
            float vv[4] = {v.x, v.y, v.z, v.w};
            #pragma unroll
            for (int q = 0; q < 4; q++) {
                uint32_t hi = f2tf(vv[q]);
                float lof = vv[q] - __uint_as_float(hi);
                Zh[j * 136 + c4 + q] = hi;
                Zl[j * 136 + c4 + q] = f2tf(lof);
            }
        }
        __syncthreads();

        float c[2][4];
        #pragma unroll
        for (int n8 = 0; n8 < 2; n8++)
            #pragma unroll
            for (int q = 0; q < 4; q++) c[n8][q] = 0.f;

        #pragma unroll 4
        for (int k0 = 0; k0 < 128; k0 += 8) {
            uint32_t ah[4], al[4];
            int rA = (wi * 16 + g) * 136 + k0 + t4;
            int rA8 = rA + 8 * 136;
            ah[0] = Gh[rA]; ah[1] = Gh[rA8]; ah[2] = Gh[rA + 4]; ah[3] = Gh[rA8 + 4];
            al[0] = Gl[rA]; al[1] = Gl[rA8]; al[2] = Gl[rA + 4]; al[3] = Gl[rA8 + 4];
            #pragma unroll
            for (int n8 = 0; n8 < 2; n8++) {
                uint32_t bh[2], bl[2];
                int rB = (wj * 16 + n8 * 8 + g) * 136 + k0 + t4;
                bh[0] = Zh[rB]; bh[1] = Zh[rB + 4];
                bl[0] = Zl[rB]; bl[1] = Zl[rB + 4];
                mma_tf32(c[n8], ah, bh);
                mma_tf32(c[n8], al, bh);
                mma_tf32(c[n8], ah, bl);
            }
        }

        #pragma unroll
        for (int n8 = 0; n8 < 2; n8++) {
            int j = jh * 32 + wj * 16 + n8 * 8 + t4 * 2;
            int i = wi * 16 + g;
            *(float2*)(cbase + (size_t)i * 64 + j) = make_float2(c[n8][0] * scale, c[n8][1] * scale);
            *(float2*)(cbase + (size_t)(i + 8) * 64 + j) = make_float2(c[n8][2] * scale, c[n8][3] * scale);
        }
    }
}

// ---------------- K2: fused attention, 384 half-blocks, occ 3, V in smem ----------------
#define K2_SMEM ((32*132 + 32*32 + 64*36 + 32*64 + 128 + 32 + 32 + 128 + 128 + 8 + 64 + 64*128) * 4)

__global__ void __launch_bounds__(256, 3) k2_attn(
    const float* __restrict__ x, const float* __restrict__ edge,
    const float* __restrict__ prior, const unsigned char* __restrict__ maskp,
    const float* __restrict__ W1, const float* __restrict__ b1,
    const float* __restrict__ W2, const float* __restrict__ b2,
    const float* __restrict__ Wfuse, const float* __restrict__ lng,
    const float* __restrict__ lnb, const float* __restrict__ pw,
    const float* __restrict__ prw, float* __restrict__ out) {
    extern __shared__ float sm[];
    float* Zs   = sm;               // 32*132 (own i-half rows of Z; becomes h)
    float* qhs  = Zs + 32 * 132;    // 32*32  (qh + b1)   } overlay: alphaT 64*36
    float* khs  = qhs + 32 * 32;    // 64*36              }
    float* Ls   = khs + 64 * 36;    // 32*64
    float* W1qs = Ls + 32 * 64;     // 4*32
    float* b1s  = W1qs + 128;       // 32
    float* W2s  = b1s + 32;         // 32
    float* lngs = W2s + 32;         // 128
    float* lnbs = lngs + 128;       // 128
    float* Wfs  = lnbs + 128;       // 8
    float* msk  = Wfs + 8;          // 64
    float* Vs   = msk + 64;         // 64*128
    float* alphaT = qhs;            // 64*36

    int bt = blockIdx.x;
    int ih = blockIdx.y;            // i-half: rows ih*32..+31
    int b = bt / 96, t = bt - b * 96;
    int tid = threadIdx.x;
    int warp = tid >> 5, lane = tid & 31;

    // ---- Phase A: loads ----
    const float* xbase = x + (size_t)((b * 64 + ih * 32) * 96 + t) * 128;
    const float* s1 = g_S1 + (size_t)(bt * 64) * SCOLS;
    #pragma unroll
    for (int it = 0; it < 4; it++) {
        int idx = tid + it * 256;
        int i = idx >> 5, c4 = (idx & 31) * 4;
        *(float4*)(Zs + i * 132 + c4) = *(const float4*)(xbase + (size_t)i * 96 * 128 + c4);
    }
    // V tile: 64 x 128 coalesced into smem
    #pragma unroll
    for (int it = 0; it < 8; it++) {
        int idx = tid + it * 256;
        int i = idx >> 5, c4 = (idx & 31) * 4;
        *(float4*)(Vs + i * 128 + c4) = *(const float4*)(s1 + (size_t)i * SCOLS + 128 + c4);
    }
    {
        int i = tid >> 3, c4 = (tid & 7) * 4;   // 32 rows x 32 cols
        *(float4*)(qhs + i * 32 + c4) = *(const float4*)(s1 + (size_t)(ih * 32 + i) * SCOLS + 256 + c4);
    }
    #pragma unroll
    for (int it = 0; it < 2; it++) {
        int idx = tid + it * 256;
        int i = idx >> 3, c4 = (idx & 7) * 4;
        *(float4*)(khs + i * 36 + c4) = *(const float4*)(s1 + (size_t)i * SCOLS + 288 + c4);
    }
    if (tid < 128) {
        int q = tid >> 5, tt = tid & 31;
        W1qs[q * 32 + tt] = W1[(256 + q) * 32 + tt];
        lngs[tid] = lng[tid];
        lnbs[tid] = lnb[tid];
    }
    if (tid < 32) { b1s[tid] = b1[tid]; W2s[tid] = W2[tid]; }
    if (tid < 5) Wfs[tid] = Wfuse[tid];
    if (tid < 64) msk[tid] = (float)maskp[b * 64 + tid];
    __syncthreads();
    // fold b1 into qhs (1024 floats)
    #pragma unroll
    for (int it = 0; it < 4; it++) {
        int idx = tid + it * 256;
        qhs[idx] += b1s[idx & 31];
    }
    __syncthreads();

    float pwv = pw[0], prwv = prw[0], b2v = b2[0];

    // ---- Phase B: logits, 2x4 tile per thread ----
    int ti = tid >> 4, tj = tid & 15;
    int i0l = ti * 2;               // local rows i0l, i0l+1
    int j0 = tj * 4;
    const float* ebase = edge + (size_t)bt * 4096 * 4 + (size_t)ih * 32 * 64 * 4;
    const float* pbase = prior + (size_t)bt * 4096 * 5 + (size_t)ih * 32 * 64 * 5;

    float4 ef[2][4];
    #pragma unroll
    for (int u = 0; u < 2; u++)
        #pragma unroll
        for (int j = 0; j < 4; j++)
            ef[u][j] = *(const float4*)(ebase + (size_t)((i0l + u) * 64 + j0 + j) * 4);

    float p[2][4];
    #pragma unroll
    for (int u = 0; u < 2; u++)
        #pragma unroll
        for (int j = 0; j < 4; j++) p[u][j] = 0.f;

    #pragma unroll
    for (int tt = 0; tt < 32; tt += 4) {
        float4 w2v = *(float4*)(W2s + tt);
        float4 wq0 = *(float4*)(W1qs + 0 * 32 + tt);
        float4 wq1 = *(float4*)(W1qs + 1 * 32 + tt);
        float4 wq2 = *(float4*)(W1qs + 2 * 32 + tt);
        float4 wq3 = *(float4*)(W1qs + 3 * 32 + tt);
        u64 w0a = pk2(wq0.x, wq0.y), w0b = pk2(wq0.z, wq0.w);
        u64 w1a = pk2(wq1.x, wq1.y), w1b = pk2(wq1.z, wq1.w);
        u64 w2a = pk2(wq2.x, wq2.y), w2b = pk2(wq2.z, wq2.w);
        u64 w3a = pk2(wq3.x, wq3.y), w3b = pk2(wq3.z, wq3.w);
        u64 qa[2], qb_[2];
        #pragma unroll
        for (int u = 0; u < 2; u++) {
            float4 q4 = *(float4*)(qhs + (i0l + u) * 32 + tt);
            qa[u] = pk2(q4.x, q4.y); qb_[u] = pk2(q4.z, q4.w);
        }
        #pragma unroll
        for (int j = 0; j < 4; j++) {
            float4 kh = *(float4*)(khs + (j0 + j) * 36 + tt);
            u64 k01 = pk2(kh.x, kh.y), k23 = pk2(kh.z, kh.w);
            #pragma unroll
            for (int u = 0; u < 2; u++) {
                u64 ex = pk2(ef[u][j].x, ef[u][j].x);
                u64 ey = pk2(ef[u][j].y, ef[u][j].y);
                u64 ez = pk2(ef[u][j].z, ef[u][j].z);
                u64 ew = pk2(ef[u][j].w, ef[u][j].w);
                u64 h01 = add2_(qa[u], k01);
                h01 = fma2_(ex, w0a, h01);
                h01 = fma2_(ey, w1a, h01);
                h01 = fma2_(ez, w2a, h01);
                h01 = fma2_(ew, w3a, h01);
                float2 hf = up2(h01);
                float pj = p[u][j];
                pj = fmaf(fmaxf(hf.x, 0.f), w2v.x, pj);
                pj = fmaf(fmaxf(hf.y, 0.f), w2v.y, pj);
                u64 h23 = add2_(qb_[u], k23);
                h23 = fma2_(ex, w0b, h23);
                h23 = fma2_(ey, w1b, h23);
                h23 = fma2_(ez, w2b, h23);
                h23 = fma2_(ew, w3b, h23);
                hf = up2(h23);
                pj = fmaf(fmaxf(hf.x, 0.f), w2v.z, pj);
                pj = fmaf(fmaxf(hf.y, 0.f), w2v.w, pj);
                p[u][j] = pj;
            }
        }
    }

    const float* cbase = g_C + (size_t)bt * 4096;
    #pragma unroll
    for (int u = 0; u < 2; u++) {
        int il = i0l + u;
        int ig = ih * 32 + il;
        float pr[20];
        const float* ap0 = pbase + (size_t)(il * 64 + j0) * 5;
        *(float4*)(pr + 0)  = *(const float4*)(ap0 + 0);
        *(float4*)(pr + 4)  = *(const float4*)(ap0 + 4);
        *(float4*)(pr + 8)  = *(const float4*)(ap0 + 8);
        *(float4*)(pr + 12) = *(const float4*)(ap0 + 12);
        *(float4*)(pr + 16) = *(const float4*)(ap0 + 16);
        float4 cnt = *(const float4*)(cbase + (size_t)ig * 64 + j0);
        float cv[4] = {cnt.x, cnt.y, cnt.z, cnt.w};
        float Lv[4];
        #pragma unroll
        for (int v = 0; v < 4; v++) {
            float Ap = pr[v*5+0]*Wfs[0] + pr[v*5+1]*Wfs[1] + pr[v*5+2]*Wfs[2]
                     + pr[v*5+3]*Wfs[3] + pr[v*5+4]*Wfs[4];
            Ap = fmaxf(Ap, 0.f);
            float L = cv[v] + pwv * (p[u][v] + b2v) + prwv * __logf(Ap + 1e-6f);
            if (msk[ig] != 0.f || msk[j0 + v] != 0.f) L = -1e9f;
            Lv[v] = L;
        }
        *(float4*)(Ls + il * 64 + j0) = make_float4(Lv[0], Lv[1], Lv[2], Lv[3]);
    }
    __syncthreads();

    // ---- Phase C: softmax (32 local rows), transposed alpha over qhs/khs ----
    #pragma unroll 1
    for (int rr = 0; rr < 4; rr++) {
        int r = warp + rr * 8;
        float v0 = Ls[r * 64 + lane], v1 = Ls[r * 64 + lane + 32];
        float m = fmaxf(v0, v1);
        #pragma unroll
        for (int o = 16; o; o >>= 1) m = fmaxf(m, __shfl_xor_sync(0xffffffffu, m, o));
        float e0 = __expf(v0 - m), e1 = __expf(v1 - m);
        float s = e0 + e1;
        #pragma unroll
        for (int o = 16; o; o >>= 1) s += __shfl_xor_sync(0xffffffffu, s, o);
        float inv = 1.f / s;
        alphaT[lane * 36 + r] = e0 * inv;
        alphaT[(lane + 32) * 36 + r] = e1 * inv;
    }
    __syncthreads();

    // ---- Phase D: h = Z + alpha @ Vt (V from smem), store into Zs ----
    int di = tid & 127, grp = tid >> 7;
    {
        int r0 = grp * 16;
        u64 acc2[8];
        #pragma unroll
        for (int q = 0; q < 8; q++)
            acc2[q] = pk2(Zs[(r0 + 2*q) * 132 + di], Zs[(r0 + 2*q + 1) * 132 + di]);
        #pragma unroll 8
        for (int jj = 0; jj < 64; jj++) {
            float vv = Vs[jj * 128 + di];
            u64 vv2 = pk2(vv, vv);
            float4 a0 = *(float4*)(alphaT + jj * 36 + r0);
            float4 a1 = *(float4*)(alphaT + jj * 36 + r0 + 4);
            float4 a2 = *(float4*)(alphaT + jj * 36 + r0 + 8);
            float4 a3 = *(float4*)(alphaT + jj * 36 + r0 + 12);
            acc2[0] = fma2_(pk2(a0.x, a0.y), vv2, acc2[0]);
            acc2[1] = fma2_(pk2(a0.z, a0.w), vv2, acc2[1]);
            acc2[2] = fma2_(pk2(a1.x, a1.y), vv2, acc2[2]);
            acc2[3] = fma2_(pk2(a1.z, a1.w), vv2, acc2[3]);
            acc2[4] = fma2_(pk2(a2.x, a2.y), vv2, acc2[4]);
            acc2[5] = fma2_(pk2(a2.z, a2.w), vv2, acc2[5]);
            acc2[6] = fma2_(pk2(a3.x, a3.y), vv2, acc2[6]);
            acc2[7] = fma2_(pk2(a3.z, a3.w), vv2, acc2[7]);
        }
        #pragma unroll
        for (int q = 0; q < 8; q++) {
            float2 f = up2(acc2[q]);
            Zs[(r0 + 2*q) * 132 + di] = f.x;
            Zs[(r0 + 2*q + 1) * 132 + di] = f.y;
        }
    }
    __syncthreads();

    // ---- Phase E: LayerNorm + masked, transposed store ----
    float* outb = out + (size_t)((b * 64) * 96 + t) * 128;
    #pragma unroll 1
    for (int rr = 0; rr < 4; rr++) {
        int r = warp + rr * 8;
        int rg = ih * 32 + r;
        float v[4];
        #pragma unroll
        for (int u = 0; u < 4; u++) v[u] = Zs[r * 132 + lane + 32 * u];
        float s = v[0] + v[1] + v[2] + v[3];
        #pragma unroll
        for (int o = 16; o; o >>= 1) s += __shfl_xor_sync(0xffffffffu, s, o);
        float mu = s * (1.f / 128.f);
        float q = 0.f;
        #pragma unroll
        for (int u = 0; u < 4; u++) { float d = v[u] - mu; q = fmaf(d, d, q); }
        #pragma unroll
        for (int o = 16; o; o >>= 1) q += __shfl_xor_sync(0xffffffffu, q, o);
        float inv = rsqrtf(q * (1.f / 128.f) + 1e-5f);
        float keep = (msk[rg] != 0.f) ? 0.f : 1.f;
        float* op = outb + (size_t)rg * 96 * 128;
        #pragma unroll
        for (int u = 0; u < 4; u++) {
            int d = lane + 32 * u;
            op[d] = ((v[u] - mu) * inv * lngs[d] + lnbs[d]) * keep;
        }
    }
}

extern "C" void kernel_launch(void* const* d_in, const int* in_sizes, int n_in,
                              void* d_out, int out_size) {
    const float* x     = (const float*)d_in[0];
    const float* edge  = (const float*)d_in[1];
    const float* prior = (const float*)d_in[2];
    const unsigned char* maskp = (const unsigned char*)d_in[3];
    const float* Wq    = (const float*)d_in[4];
    const float* Wk    = (const float*)d_in[5];
    const float* Wv    = (const float*)d_in[6];
    const float* W1    = (const float*)d_in[7];
    const float* b1    = (const float*)d_in[8];
    const float* W2    = (const float*)d_in[9];
    const float* b2    = (const float*)d_in[10];
    const float* Wfuse = (const float*)d_in[11];
    const float* Wth   = (const float*)d_in[12];
    const float* lng   = (const float*)d_in[13];
    const float* lnb   = (const float*)d_in[14];
    const float* pw    = (const float*)d_in[15];
    const float* prw   = (const float*)d_in[16];
    float* out = (float*)d_out;

    static int inited = 0;
    if (!inited) {
        cudaFuncSetAttribute(k1_gemm, cudaFuncAttributeMaxDynamicSharedMemorySize, K1_SMEM);
        cudaFuncSetAttribute(k1b_content, cudaFuncAttributeMaxDynamicSharedMemorySize, K1B_SMEM);
        cudaFuncSetAttribute(k2_attn, cudaFuncAttributeMaxDynamicSharedMemorySize, K2_SMEM);
        inited = 1;
    }

    k0_fuse<<<dim3(10, 4, 4), 256>>>(Wq, Wk, Wv, W1, Wth);
    k1_gemm<<<dim3(96, 3), 256, K1_SMEM>>>(x);
    k1b_content<<<192, 256, K1B_SMEM>>>(x);
    k2_attn<<<dim3(192, 2), 256, K2_SMEM>>>(x, edge, prior, maskp, W1, b1, W2, b2,
                                            Wfuse, lng, lnb, pw, prw, out);
}

// round 15
// speedup vs baseline: 1.0433x; 1.0433x over previous
#include <cuda_runtime.h>
#include <cstdint>

#define BT_TOT 192
#define NN 64
#define DM 128
#define TT 96
#define SCOLS 320   // 0-127: G=Z@(Wq Wk^T), 128-255: Vt=Z@(Wv Wth), 256-287: qh, 288-319: kh

__device__ float g_Wpart[4][128 * SCOLS];   // K-split partial products of Wcat
__device__ float g_S1[12288 * SCOLS];
__device__ float g_C[192 * 64 * 64];        // content logits (pre-scaled)

typedef unsigned long long u64;
__device__ __forceinline__ u64 pk2(float lo, float hi) {
    u64 r; asm("mov.b64 %0,{%1,%2};" : "=l"(r) : "f"(lo), "f"(hi)); return r;
}
__device__ __forceinline__ float2 up2(u64 v) {
    float2 f; asm("mov.b64 {%0,%1},%2;" : "=f"(f.x), "=f"(f.y) : "l"(v)); return f;
}
__device__ __forceinline__ u64 fma2_(u64 a, u64 b, u64 c) {
    u64 d; asm("fma.rn.f32x2 %0,%1,%2,%3;" : "=l"(d) : "l"(a), "l"(b), "l"(c)); return d;
}
__device__ __forceinline__ u64 add2_(u64 a, u64 b) {
    u64 d; asm("add.rn.f32x2 %0,%1,%2;" : "=l"(d) : "l"(a), "l"(b)); return d;
}

// ---------------- K0: partial Wcat products, 4-way K-split, 160 blocks ----------------
__global__ void __launch_bounds__(256) k0_fuse(
    const float* __restrict__ Wq, const float* __restrict__ Wk,
    const float* __restrict__ Wv, const float* __restrict__ W1,
    const float* __restrict__ Wth) {
    __shared__ float As[32 * 36];   // [row][m']
    __shared__ float Bs[32 * 36];   // [col][m']
    int ct = blockIdx.x;   // 0..9
    int rt = blockIdx.y;   // 0..3
    int kh = blockIdx.z;   // 0..3  (K chunk)
    int r0 = rt * 32, mo = kh * 32;
    int tid = threadIdx.x;

    const float* Asrc = (ct < 4) ? Wq : (ct < 8) ? Wv : (ct == 8) ? Wq : Wk;
    {
        int i = tid >> 3, c4 = (tid & 7) * 4;
        *(float4*)(As + i * 36 + c4) = *(const float4*)(Asrc + (r0 + i) * 128 + mo + c4);
    }
    if (ct < 4) {
        int c = tid >> 3, m4 = (tid & 7) * 4;
        *(float4*)(Bs + c * 36 + m4) = *(const float4*)(Wk + (ct * 32 + c) * 128 + mo + m4);
    } else if (ct < 8) {
        int m = tid >> 3, c4 = (tid & 7) * 4;
        float4 v = *(const float4*)(Wth + (mo + m) * 128 + (ct - 4) * 32 + c4);
        Bs[(c4 + 0) * 36 + m] = v.x;
        Bs[(c4 + 1) * 36 + m] = v.y;
        Bs[(c4 + 2) * 36 + m] = v.z;
        Bs[(c4 + 3) * 36 + m] = v.w;
    } else {
        int off = (ct == 9) ? 128 : 0;
        int m = tid >> 3, c4 = (tid & 7) * 4;
        float4 v = *(const float4*)(W1 + (off + mo + m) * 32 + c4);
        Bs[(c4 + 0) * 36 + m] = v.x;
        Bs[(c4 + 1) * 36 + m] = v.y;
        Bs[(c4 + 2) * 36 + m] = v.z;
        Bs[(c4 + 3) * 36 + m] = v.w;
    }
    __syncthreads();

    int tx = tid & 15, ty = tid >> 4;
    u64 a00 = 0, a01 = 0, a10 = 0, a11 = 0;
    #pragma unroll
    for (int m = 0; m < 32; m += 4) {
        float4 x0 = *(float4*)(As + (ty * 2 + 0) * 36 + m);
        float4 x1 = *(float4*)(As + (ty * 2 + 1) * 36 + m);
        float4 y0 = *(float4*)(Bs + (tx * 2 + 0) * 36 + m);
        float4 y1 = *(float4*)(Bs + (tx * 2 + 1) * 36 + m);
        u64 x0a = pk2(x0.x, x0.y), x0b = pk2(x0.z, x0.w);
        u64 x1a = pk2(x1.x, x1.y), x1b = pk2(x1.z, x1.w);
        u64 y0a = pk2(y0.x, y0.y), y0b = pk2(y0.z, y0.w);
        u64 y1a = pk2(y1.x, y1.y), y1b = pk2(y1.z, y1.w);
        a00 = fma2_(x0a, y0a, a00); a00 = fma2_(x0b, y0b, a00);
        a01 = fma2_(x0a, y1a, a01); a01 = fma2_(x0b, y1b, a01);
        a10 = fma2_(x1a, y0a, a10); a10 = fma2_(x1b, y0b, a10);
        a11 = fma2_(x1a, y1a, a11); a11 = fma2_(x1b, y1b, a11);
    }
    float2 f;
    int orow = r0 + ty * 2, ocol = ct * 32 + tx * 2;
    float* wp = g_Wpart[kh];
    f = up2(a00); wp[(orow + 0) * SCOLS + ocol + 0] = f.x + f.y;
    f = up2(a01); wp[(orow + 0) * SCOLS + ocol + 1] = f.x + f.y;
    f = up2(a10); wp[(orow + 1) * SCOLS + ocol + 0] = f.x + f.y;
    f = up2(a11); wp[(orow + 1) * SCOLS + ocol + 1] = f.x + f.y;
}

// ---------------- TF32 helpers ----------------
__device__ __forceinline__ uint32_t f2tf(float f) {
    uint32_t u; asm("cvt.rna.tf32.f32 %0, %1;" : "=r"(u) : "f"(f)); return u;
}
__device__ __forceinline__ void mma_tf32(float* c, const uint32_t* a, const uint32_t* b) {
    asm volatile("mma.sync.aligned.m16n8k8.row.col.f32.tf32.tf32.f32 "
        "{%0,%1,%2,%3}, {%4,%5,%6,%7}, {%8,%9}, {%0,%1,%2,%3};"
        : "+f"(c[0]), "+f"(c[1]), "+f"(c[2]), "+f"(c[3])
        : "r"(a[0]), "r"(a[1]), "r"(a[2]), "r"(a[3]), "r"(b[0]), "r"(b[1]));
}

// ---------------- K1: S1 = Z @ Wcat via 3xTF32 tensor cores ----------------
#define K1_SMEM ((128*36*2 + 32*136*2) * 4)

__global__ void __launch_bounds__(256) k1_gemm(const float* __restrict__ x) {
    extern __shared__ uint32_t smk1[];
    uint32_t* Ah = smk1;                 // 128 x 36
    uint32_t* Al = Ah + 128 * 36;
    uint32_t* Bh = Al + 128 * 36;        // 32 x 136
    uint32_t* Bl = Bh + 32 * 136;

    int m0 = blockIdx.x * 128;
    int n0 = blockIdx.y * 128;
    int tid = threadIdx.x;
    int lane = tid & 31, warp = tid >> 5;
    int g = lane >> 2, t4 = lane & 3;
    int wm = warp >> 2, wn = warp & 3;
    int mb = wm * 64, nb = wn * 32;

    float c[4][4][4];
    #pragma unroll
    for (int im = 0; im < 4; im++)
        #pragma unroll
        for (int in_ = 0; in_ < 4; in_++)
            #pragma unroll
            for (int q = 0; q < 4; q++) c[im][in_][q] = 0.f;

    for (int kk = 0; kk < 128; kk += 32) {
        #pragma unroll
        for (int it = 0; it < 4; it++) {
            int idx = tid + it * 256;
            int i = idx >> 3, c4 = (idx & 7) * 4;
            int r = m0 + i;
            int bt = r >> 6, n = r & 63;
            int b = bt / 96, t = bt - b * 96;
            float4 v = *(const float4*)(x + (size_t)(((b * 64 + n) * 96 + t)) * 128 + kk + c4);
            float vv[4] = {v.x, v.y, v.z, v.w};
            #pragma unroll
            for (int q = 0; q < 4; q++) {
                uint32_t hi = f2tf(vv[q]);
                float lof = vv[q] - __uint_as_float(hi);
                Ah[i * 36 + c4 + q] = hi;
                Al[i * 36 + c4 + q] = f2tf(lof);
            }
        }
        #pragma unroll
        for (int it = 0; it < 4; it++) {
            int idx = tid + it * 256;
            int kr = idx >> 5, c4 = (idx & 31) * 4;
            int col = n0 + c4;
            float4 v = make_float4(0.f, 0.f, 0.f, 0.f);
            if (col < SCOLS) {
                size_t off = (size_t)(kk + kr) * SCOLS + col;
                float4 v0 = *(const float4*)(g_Wpart[0] + off);
                float4 v1 = *(const float4*)(g_Wpart[1] + off);
                float4 v2 = *(const float4*)(g_Wpart[2] + off);
                float4 v3 = *(const float4*)(g_Wpart[3] + off);
                v.x = (v0.x + v1.x) + (v2.x + v3.x);
                v.y = (v0.y + v1.y) + (v2.y + v3.y);
                v.z = (v0.z + v1.z) + (v2.z + v3.z);
                v.w = (v0.w + v1.w) + (v2.w + v3.w);
            }
            float vv[4] = {v.x, v.y, v.z, v.w};
            #pragma unroll
            for (int q = 0; q < 4; q++) {
                uint32_t hi = f2tf(vv[q]);
                float lof = vv[q] - __uint_as_float(hi);
                Bh[kr * 136 + c4 + q] = hi;
                Bl[kr * 136 + c4 + q] = f2tf(lof);
            }
        }
        __syncthreads();

        #pragma unroll
        for (int ks = 0; ks < 4; ks++) {
            int k0 = ks * 8;
            uint32_t ahi[4][4], alo[4][4], bhi[4][2], blo[4][2];
            #pragma unroll
            for (int im = 0; im < 4; im++) {
                int rA = (mb + im * 16 + g) * 36 + k0 + t4;
                int rA8 = rA + 8 * 36;
                ahi[im][0] = Ah[rA];      ahi[im][1] = Ah[rA8];
                ahi[im][2] = Ah[rA + 4];  ahi[im][3] = Ah[rA8 + 4];
                alo[im][0] = Al[rA];      alo[im][1] = Al[rA8];
                alo[im][2] = Al[rA + 4];  alo[im][3] = Al[rA8 + 4];
            }
            #pragma unroll
            for (int in_ = 0; in_ < 4; in_++) {
                int colB = nb + in_ * 8 + g;
                bhi[in_][0] = Bh[(k0 + t4) * 136 + colB];
                bhi[in_][1] = Bh[(k0 + t4 + 4) * 136 + colB];
                blo[in_][0] = Bl[(k0 + t4) * 136 + colB];
                blo[in_][1] = Bl[(k0 + t4 + 4) * 136 + colB];
            }
            #pragma unroll
            for (int im = 0; im < 4; im++)
                #pragma unroll
                for (int in_ = 0; in_ < 4; in_++) {
                    mma_tf32(c[im][in_], ahi[im], bhi[in_]);
                    mma_tf32(c[im][in_], alo[im], bhi[in_]);
                    mma_tf32(c[im][in_], ahi[im], blo[in_]);
                }
        }
        __syncthreads();
    }

    #pragma unroll
    for (int im = 0; im < 4; im++)
        #pragma unroll
        for (int in_ = 0; in_ < 4; in_++) {
            int row = m0 + mb + im * 16 + g;
            int col = n0 + nb + in_ * 8 + t4 * 2;
            if (col < SCOLS) {
                *(float2*)(g_S1 + (size_t)row * SCOLS + col) = make_float2(c[im][in_][0], c[im][in_][1]);
                *(float2*)(g_S1 + (size_t)(row + 8) * SCOLS + col) = make_float2(c[im][in_][2], c[im][in_][3]);
            }
        }
}

// ---------------- K1B: content[bt] = G @ Z^T (scaled), 3xTF32 ----------------
#define K1B_SMEM ((64*136*2 + 32*136*2) * 4)

__global__ void __launch_bounds__(256) k1b_content(const float* __restrict__ x) {
    extern __shared__ uint32_t smc[];
    uint32_t* Gh = smc;                  // 64 x 136
    uint32_t* Gl = Gh + 64 * 136;
    uint32_t* Zh = Gl + 64 * 136;        // 32 x 136
    uint32_t* Zl = Zh + 32 * 136;

    int bt = blockIdx.x;
    int b = bt / 96, t = bt - b * 96;
    int tid = threadIdx.x;
    int lane = tid & 31, warp = tid >> 5;
    int g = lane >> 2, t4 = lane & 3;
    int wi = warp >> 1, wj = warp & 1;

    const float* s1 = g_S1 + (size_t)(bt * 64) * SCOLS;
    #pragma unroll
    for (int it = 0; it < 8; it++) {
        int idx = tid + it * 256;
        int i = idx >> 5, c4 = (idx & 31) * 4;
        float4 v = *(const float4*)(s1 + (size_t)i * SCOLS + c4);
        float vv[4] = {v.x, v.y, v.z, v.w};
        #pragma unroll
        for (int q = 0; q < 4; q++) {
            uint32_t hi = f2tf(vv[q]);
            float lof = vv[q] - __uint_as_float(hi);
            Gh[i * 136 + c4 + q] = hi;
            Gl[i * 136 + c4 + q] = f2tf(lof);
        }
    }

    const float scale = 0.08838834764831845f;
    float* cbase = g_C + (size_t)bt * 4096;

    for (int jh = 0; jh < 2; jh++) {
        __syncthreads();
        #pragma unroll
        for (int it = 0; it < 4; it++) {
            int idx = tid + it * 256;
            int j = idx >> 5, c4 = (idx & 31) * 4;
            float4 v = *(const float4*)(x + (size_t)(((b * 64 + jh * 32 + j) * 96 + t)) * 128 + c4);
            float vv[4] = {v.x, v.y, v.z, v.w};
            #pragma unroll
            for (int q = 0; q < 4; q++) {
                uint32_t hi = f2tf(vv[q]);
                float lof = vv[q] - __uint_as_float(hi);
                Zh[j * 136 + c4 + q] = hi;
                Zl[j * 136 + c4 + q] = f2tf(lof);
            }
        }
        __syncthreads();

        float c[2][4];
        #pragma unroll
        for (int n8 = 0; n8 < 2; n8++)
            #pragma unroll
            for (int q = 0; q < 4; q++) c[n8][q] = 0.f;

        #pragma unroll 4
        for (int k0 = 0; k0 < 128; k0 += 8) {
            uint32_t ah[4], al[4];
            int rA = (wi * 16 + g) * 136 + k0 + t4;
            int rA8 = rA + 8 * 136;
            ah[0] = Gh[rA]; ah[1] = Gh[rA8]; ah[2] = Gh[rA + 4]; ah[3] = Gh[rA8 + 4];
            al[0] = Gl[rA]; al[1] = Gl[rA8]; al[2] = Gl[rA + 4]; al[3] = Gl[rA8 + 4];
            #pragma unroll
            for (int n8 = 0; n8 < 2; n8++) {
                uint32_t bh[2], bl[2];
                int rB = (wj * 16 + n8 * 8 + g) * 136 + k0 + t4;
                bh[0] = Zh[rB]; bh[1] = Zh[rB + 4];
                bl[0] = Zl[rB]; bl[1] = Zl[rB + 4];
                mma_tf32(c[n8], ah, bh);
                mma_tf32(c[n8], al, bh);
                mma_tf32(c[n8], ah, bl);
            }
        }

        #pragma unroll
        for (int n8 = 0; n8 < 2; n8++) {
            int j = jh * 32 + wj * 16 + n8 * 8 + t4 * 2;
            int i = wi * 16 + g;
            *(float2*)(cbase + (size_t)i * 64 + j) = make_float2(c[n8][0] * scale, c[n8][1] * scale);
            *(float2*)(cbase + (size_t)(i + 8) * 64 + j) = make_float2(c[n8][2] * scale, c[n8][3] * scale);
        }
    }
}

// ---------------- K2: fused attention, 384 half-blocks, occ 3 ----------------
#define K2_SMEM ((32*132 + 32*32 + 64*36 + 32*64 + 128 + 32 + 32 + 128 + 128 + 8 + 64) * 4)

__global__ void __launch_bounds__(256, 3) k2_attn(
    const float* __restrict__ x, const float* __restrict__ edge,
    const float* __restrict__ prior, const unsigned char* __restrict__ maskp,
    const float* __restrict__ W1, const float* __restrict__ b1,
    const float* __restrict__ W2, const float* __restrict__ b2,
    const float* __restrict__ Wfuse, const float* __restrict__ lng,
    const float* __restrict__ lnb, const float* __restrict__ pw,
    const float* __restrict__ prw, float* __restrict__ out) {
    extern __shared__ float sm[];
    float* Zs   = sm;               // 32*132 (own i-half rows of Z; becomes h)
    float* qhs  = Zs + 32 * 132;    // 32*32  (qh + b1)   } overlay: alphaT 64*36
    float* khs  = qhs + 32 * 32;    // 64*36              }
    float* Ls   = khs + 64 * 36;    // 32*64
    float* W1qs = Ls + 32 * 64;     // 4*32
    float* b1s  = W1qs + 128;       // 32
    float* W2s  = b1s + 32;         // 32
    float* lngs = W2s + 32;         // 128
    float* lnbs = lngs + 128;       // 128
    float* Wfs  = lnbs + 128;       // 8
    float* msk  = Wfs + 8;          // 64
    float* alphaT = qhs;            // 64*36

    int bt = blockIdx.x;
    int ih = blockIdx.y;            // i-half: rows ih*32..+31
    int b = bt / 96, t = bt - b * 96;
    int tid = threadIdx.x;
    int warp = tid >> 5, lane = tid & 31;

    // ---- Phase A: loads ----
    const float* xbase = x + (size_t)((b * 64 + ih * 32) * 96 + t) * 128;
    const float* s1 = g_S1 + (size_t)(bt * 64) * SCOLS;
    #pragma unroll
    for (int it = 0; it < 4; it++) {
        int idx = tid + it * 256;
        int i = idx >> 5, c4 = (idx & 31) * 4;
        *(float4*)(Zs + i * 132 + c4) = *(const float4*)(xbase + (size_t)i * 96 * 128 + c4);
    }
    {
        int i = tid >> 3, c4 = (tid & 7) * 4;   // 32 rows x 32 cols
        *(float4*)(qhs + i * 32 + c4) = *(const float4*)(s1 + (size_t)(ih * 32 + i) * SCOLS + 256 + c4);
    }
    #pragma unroll
    for (int it = 0; it < 2; it++) {
        int idx = tid + it * 256;
        int i = idx >> 3, c4 = (idx & 7) * 4;
        *(float4*)(khs + i * 36 + c4) = *(const float4*)(s1 + (size_t)i * SCOLS + 288 + c4);
    }
    if (tid < 128) {
        int q = tid >> 5, tt = tid & 31;
        W1qs[q * 32 + tt] = W1[(256 + q) * 32 + tt];
        lngs[tid] = lng[tid];
        lnbs[tid] = lnb[tid];
    }
    if (tid < 32) { b1s[tid] = b1[tid]; W2s[tid] = W2[tid]; }
    if (tid < 5) Wfs[tid] = Wfuse[tid];
    if (tid < 64) msk[tid] = (float)maskp[b * 64 + tid];
    __syncthreads();
    // fold b1 into qhs (1024 floats)
    #pragma unroll
    for (int it = 0; it < 4; it++) {
        int idx = tid + it * 256;
        qhs[idx] += b1s[idx & 31];
    }
    __syncthreads();

    float pwv = pw[0], prwv = prw[0], b2v = b2[0];

    // ---- Phase B: logits, 2x4 tile per thread ----
    int ti = tid >> 4, tj = tid & 15;
    int i0l = ti * 2;               // local rows i0l, i0l+1
    int j0 = tj * 4;
    const float* ebase = edge + (size_t)bt * 4096 * 4 + (size_t)ih * 32 * 64 * 4;
    const float* pbase = prior + (size_t)bt * 4096 * 5 + (size_t)ih * 32 * 64 * 5;

    float4 ef[2][4];
    #pragma unroll
    for (int u = 0; u < 2; u++)
        #pragma unroll
        for (int j = 0; j < 4; j++)
            ef[u][j] = *(const float4*)(ebase + (size_t)((i0l + u) * 64 + j0 + j) * 4);

    float p[2][4];
    #pragma unroll
    for (int u = 0; u < 2; u++)
        #pragma unroll
        for (int j = 0; j < 4; j++) p[u][j] = 0.f;

    #pragma unroll
    for (int tt = 0; tt < 32; tt += 4) {
        float4 w2v = *(float4*)(W2s + tt);
        float4 wq0 = *(float4*)(W1qs + 0 * 32 + tt);
        float4 wq1 = *(float4*)(W1qs + 1 * 32 + tt);
        float4 wq2 = *(float4*)(W1qs + 2 * 32 + tt);
        float4 wq3 = *(float4*)(W1qs + 3 * 32 + tt);
        u64 w0a = pk2(wq0.x, wq0.y), w0b = pk2(wq0.z, wq0.w);
        u64 w1a = pk2(wq1.x, wq1.y), w1b = pk2(wq1.z, wq1.w);
        u64 w2a = pk2(wq2.x, wq2.y), w2b = pk2(wq2.z, wq2.w);
        u64 w3a = pk2(wq3.x, wq3.y), w3b = pk2(wq3.z, wq3.w);
        u64 qa[2], qb_[2];
        #pragma unroll
        for (int u = 0; u < 2; u++) {
            float4 q4 = *(float4*)(qhs + (i0l + u) * 32 + tt);
            qa[u] = pk2(q4.x, q4.y); qb_[u] = pk2(q4.z, q4.w);
        }
        #pragma unroll
        for (int j = 0; j < 4; j++) {
            float4 kh = *(float4*)(khs + (j0 + j) * 36 + tt);
            u64 k01 = pk2(kh.x, kh.y), k23 = pk2(kh.z, kh.w);
            #pragma unroll
            for (int u = 0; u < 2; u++) {
                u64 ex = pk2(ef[u][j].x, ef[u][j].x);
                u64 ey = pk2(ef[u][j].y, ef[u][j].y);
                u64 ez = pk2(ef[u][j].z, ef[u][j].z);
                u64 ew = pk2(ef[u][j].w, ef[u][j].w);
                u64 h01 = add2_(qa[u], k01);
                h01 = fma2_(ex, w0a, h01);
                h01 = fma2_(ey, w1a, h01);
                h01 = fma2_(ez, w2a, h01);
                h01 = fma2_(ew, w3a, h01);
                float2 hf = up2(h01);
                float pj = p[u][j];
                pj = fmaf(fmaxf(hf.x, 0.f), w2v.x, pj);
                pj = fmaf(fmaxf(hf.y, 0.f), w2v.y, pj);
                u64 h23 = add2_(qb_[u], k23);
                h23 = fma2_(ex, w0b, h23);
                h23 = fma2_(ey, w1b, h23);
                h23 = fma2_(ez, w2b, h23);
                h23 = fma2_(ew, w3b, h23);
                hf = up2(h23);
                pj = fmaf(fmaxf(hf.x, 0.f), w2v.z, pj);
                pj = fmaf(fmaxf(hf.y, 0.f), w2v.w, pj);
                p[u][j] = pj;
            }
        }
    }

    const float* cbase = g_C + (size_t)bt * 4096;
    #pragma unroll
    for (int u = 0; u < 2; u++) {
        int il = i0l + u;
        int ig = ih * 32 + il;
        float pr[20];
        const float* ap0 = pbase + (size_t)(il * 64 + j0) * 5;
        *(float4*)(pr + 0)  = *(const float4*)(ap0 + 0);
        *(float4*)(pr + 4)  = *(const float4*)(ap0 + 4);
        *(float4*)(pr + 8)  = *(const float4*)(ap0 + 8);
        *(float4*)(pr + 12) = *(const float4*)(ap0 + 12);
        *(float4*)(pr + 16) = *(const float4*)(ap0 + 16);
        float4 cnt = *(const float4*)(cbase + (size_t)ig * 64 + j0);
        float cv[4] = {cnt.x, cnt.y, cnt.z, cnt.w};
        float Lv[4];
        #pragma unroll
        for (int v = 0; v < 4; v++) {
            float Ap = pr[v*5+0]*Wfs[0] + pr[v*5+1]*Wfs[1] + pr[v*5+2]*Wfs[2]
                     + pr[v*5+3]*Wfs[3] + pr[v*5+4]*Wfs[4];
            Ap = fmaxf(Ap, 0.f);
            float L = cv[v] + pwv * (p[u][v] + b2v) + prwv * __logf(Ap + 1e-6f);
            if (msk[ig] != 0.f || msk[j0 + v] != 0.f) L = -1e9f;
            Lv[v] = L;
        }
        *(float4*)(Ls + il * 64 + j0) = make_float4(Lv[0], Lv[1], Lv[2], Lv[3]);
    }
    __syncthreads();

    // ---- Phase C: softmax (32 local rows), transposed alpha over qhs/khs ----
    #pragma unroll 1
    for (int rr = 0; rr < 4; rr++) {
        int r = warp + rr * 8;
        float v0 = Ls[r * 64 + lane], v1 = Ls[r * 64 + lane + 32];
        float m = fmaxf(v0, v1);
        #pragma unroll
        for (int o = 16; o; o >>= 1) m = fmaxf(m, __shfl_xor_sync(0xffffffffu, m, o));
        float e0 = __expf(v0 - m), e1 = __expf(v1 - m);
        float s = e0 + e1;
        #pragma unroll
        for (int o = 16; o; o >>= 1) s += __shfl_xor_sync(0xffffffffu, s, o);
        float inv = 1.f / s;
        alphaT[lane * 36 + r] = e0 * inv;
        alphaT[(lane + 32) * 36 + r] = e1 * inv;
    }
    __syncthreads();

    // ---- Phase D: h = Z + alpha @ Vt, 8 rows x 2 cols per thread ----
    // grp = tid>>6 owns local rows grp*8..+7; 64 threads cover 128 cols as float2
    {
        int di2 = (tid & 63) * 2;
        int grp = tid >> 6;
        int r0 = grp * 8;
        const float* vrow = g_S1 + (size_t)(bt * 64) * SCOLS + 128 + di2;
        u64 acc2[8];
        #pragma unroll
        for (int q = 0; q < 8; q++)
            acc2[q] = *(const u64*)(Zs + (r0 + q) * 132 + di2);
        #pragma unroll 8
        for (int jj = 0; jj < 64; jj++) {
            float2 vv = __ldg((const float2*)(vrow + (size_t)jj * SCOLS));
            u64 vv2 = pk2(vv.x, vv.y);
            float4 a0 = *(float4*)(alphaT + jj * 36 + r0);
            float4 a1 = *(float4*)(alphaT + jj * 36 + r0 + 4);
            acc2[0] = fma2_(pk2(a0.x, a0.x), vv2, acc2[0]);
            acc2[1] = fma2_(pk2(a0.y, a0.y), vv2, acc2[1]);
            acc2[2] = fma2_(pk2(a0.z, a0.z), vv2, acc2[2]);
            acc2[3] = fma2_(pk2(a0.w, a0.w), vv2, acc2[3]);
            acc2[4] = fma2_(pk2(a1.x, a1.x), vv2, acc2[4]);
            acc2[5] = fma2_(pk2(a1.y, a1.y), vv2, acc2[5]);
            acc2[6] = fma2_(pk2(a1.z, a1.z), vv2, acc2[6]);
            acc2[7] = fma2_(pk2(a1.w, a1.w), vv2, acc2[7]);
        }
        #pragma unroll
        for (int q = 0; q < 8; q++)
            *(u64*)(Zs + (r0 + q) * 132 + di2) = acc2[q];
    }
    __syncthreads();

    // ---- Phase E: LayerNorm + masked, transposed store ----
    float* outb = out + (size_t)((b * 64) * 96 + t) * 128;
    #pragma unroll 1
    for (int rr = 0; rr < 4; rr++) {
        int r = warp + rr * 8;
        int rg = ih * 32 + r;
        float v[4];
        #pragma unroll
        for (int u = 0; u < 4; u++) v[u] = Zs[r * 132 + lane + 32 * u];
        float s = v[0] + v[1] + v[2] + v[3];
        #pragma unroll
        for (int o = 16; o; o >>= 1) s += __shfl_xor_sync(0xffffffffu, s, o);
        float mu = s * (1.f / 128.f);
        float q = 0.f;
        #pragma unroll
        for (int u = 0; u < 4; u++) { float d = v[u] - mu; q = fmaf(d, d, q); }
        #pragma unroll
        for (int o = 16; o; o >>= 1) q += __shfl_xor_sync(0xffffffffu, q, o);
        float inv = rsqrtf(q * (1.f / 128.f) + 1e-5f);
        float keep = (msk[rg] != 0.f) ? 0.f : 1.f;
        float* op = outb + (size_t)rg * 96 * 128;
        #pragma unroll
        for (int u = 0; u < 4; u++) {
            int d = lane + 32 * u;
            op[d] = ((v[u] - mu) * inv * lngs[d] + lnbs[d]) * keep;
        }
    }
}

extern "C" void kernel_launch(void* const* d_in, const int* in_sizes, int n_in,
                              void* d_out, int out_size) {
    const float* x     = (const float*)d_in[0];
    const float* edge  = (const float*)d_in[1];
    const float* prior = (const float*)d_in[2];
    const unsigned char* maskp = (const unsigned char*)d_in[3];
    const float* Wq    = (const float*)d_in[4];
    const float* Wk    = (const float*)d_in[5];
    const float* Wv    = (const float*)d_in[6];
    const float* W1    = (const float*)d_in[7];
    const float* b1    = (const float*)d_in[8];
    const float* W2    = (const float*)d_in[9];
    const float* b2    = (const float*)d_in[10];
    const float* Wfuse = (const float*)d_in[11];
    const float* Wth   = (const float*)d_in[12];
    const float* lng   = (const float*)d_in[13];
    const float* lnb   = (const float*)d_in[14];
    const float* pw    = (const float*)d_in[15];
    const float* prw   = (const float*)d_in[16];
    float* out = (float*)d_out;

    static int inited = 0;
    if (!inited) {
        cudaFuncSetAttribute(k1_gemm, cudaFuncAttributeMaxDynamicSharedMemorySize, K1_SMEM);
        cudaFuncSetAttribute(k1b_content, cudaFuncAttributeMaxDynamicSharedMemorySize, K1B_SMEM);
        cudaFuncSetAttribute(k2_attn, cudaFuncAttributeMaxDynamicSharedMemorySize, K2_SMEM);
        inited = 1;
    }

    k0_fuse<<<dim3(10, 4, 4), 256>>>(Wq, Wk, Wv, W1, Wth);
    k1_gemm<<<dim3(96, 3), 256, K1_SMEM>>>(x);
    k1b_content<<<192, 256, K1B_SMEM>>>(x);
    k2_attn<<<dim3(192, 2), 256, K2_SMEM>>>(x, edge, prior, maskp, W1, b1, W2, b2,
                                            Wfuse, lng, lnb, pw, prw, out);
}